// round 5
// baseline (speedup 1.0000x reference)
#include <cuda_runtime.h>

#define NN 100000
#define NE 1600000
#define CH 64

typedef unsigned long long ull;

// Scratch (device globals — no allocation allowed)
__device__ __align__(16) float g_q[NN*CH];
__device__ __align__(16) float g_k[NN*CH];
__device__ __align__(16) float g_v[NN*CH];
__device__ __align__(16) float g_skip[NN*CH];
__device__ __align__(16) float g_agg[NN*CH];
__device__ float g_den[NN];
__device__ double g_red[2];
__device__ int g_idx64;

// All four weight matrices, K-major rows: c_W[m][c][j] = W_m[c][4j..4j+3]
// 4*64*64*4B = 65536 B = exactly the 64KB user constant bank.
__constant__ float4 c_W[4][64][16];

__device__ __forceinline__ ull ffma2(ull a, ull b, ull c){
    ull d;
    asm("fma.rn.f32x2 %0, %1, %2, %3;" : "=l"(d) : "l"(a), "l"(b), "l"(c));
    return d;
}
__device__ __forceinline__ float hadd2(ull a){
    float x, y;
    asm("mov.b64 {%0, %1}, %2;" : "=f"(x), "=f"(y) : "l"(a));
    return x + y;
}

// ---------------------------------------------------------------------------
// zero accumulators + global reduction cells (single kernel)
// ---------------------------------------------------------------------------
__global__ void k_zero(){
    int i = blockIdx.x*blockDim.x + threadIdx.x;          // NN*16 float4
    if (i < NN*16)
        reinterpret_cast<float4*>(g_agg)[i] = make_float4(0.f,0.f,0.f,0.f);
    if (i < NN/4)
        reinterpret_cast<float4*>(g_den)[i] = make_float4(0.f,0.f,0.f,0.f);
    if (i == 0){ g_red[0] = 0.0; g_red[1] = 0.0; }
}

// ---------------------------------------------------------------------------
// detect dtype of edge_index (int64 vs int32), 1 warp
// ---------------------------------------------------------------------------
__global__ void k_detect(const unsigned int* __restrict__ ei32){
    unsigned int hi = ei32[2*threadIdx.x + 1];
    unsigned int b = __ballot_sync(0xffffffffu, hi != 0u);
    if (threadIdx.x == 0) g_idx64 = (b == 0u);
}

// ---------------------------------------------------------------------------
// qkvs v4: W in __constant__ (uniform LDCU port — zero smem/L1 crossbar
// traffic), x row in 64 registers loaded once from GMEM. No shared memory.
// warp-task gt in [0, 6250): half = gt&1 (0: euc -> q,skip; 1: geo -> k,v),
// node = (gt>>1)*32 + lane  (3125*32 = 100000 exactly; no tail predication).
// ---------------------------------------------------------------------------
__global__ void __launch_bounds__(128, 4) k_qkvs(
    const float* __restrict__ geo, const float* __restrict__ euc,
    const float* __restrict__ bq, const float* __restrict__ bk,
    const float* __restrict__ bv, const float* __restrict__ bs)
{
    const int gt = blockIdx.x*4 + (threadIdx.x >> 5);
    if (gt >= 6250) return;
    const int lane = threadIdx.x & 31;
    const int half = gt & 1;
    const int node = (gt >> 1)*32 + lane;

    const float* X = half ? geo : euc;
    const int   mA = half ? 1 : 0;         // k : q
    const int   mB = half ? 2 : 3;         // v : skip
    float* OA      = half ? g_k : g_q;
    float* OB      = half ? g_v : g_skip;
    const float* BA = half ? bk : bq;
    const float* BB = half ? bv : bs;

    // x row -> 32 f32x2 registers (row read exactly once per program)
    ull x[32];
    {
        const float4* xr = reinterpret_cast<const float4*>(X + (size_t)node*CH);
        #pragma unroll
        for (int j = 0; j < 16; j++){
            float4 v = xr[j];
            x[2*j]   = (ull)__float_as_uint(v.y) << 32 | __float_as_uint(v.x);
            x[2*j+1] = (ull)__float_as_uint(v.w) << 32 | __float_as_uint(v.z);
        }
    }

    #pragma unroll 1
    for (int mm = 0; mm < 2; mm++){
        const int m = mm ? mB : mA;
        float* O = mm ? OB : OA;
        const float* B = mm ? BB : BA;
        float4 buf;
        #pragma unroll 4
        for (int c = 0; c < 64; c++){
            const ulonglong2* wp =
                reinterpret_cast<const ulonglong2*>(&c_W[m][c][0]);
            ull a0 = 0ull, a1 = 0ull;
            #pragma unroll
            for (int j = 0; j < 16; j++){
                ulonglong2 w2 = wp[j];          // LDCU.128 (uniform address)
                a0 = ffma2(x[2*j],   w2.x, a0);
                a1 = ffma2(x[2*j+1], w2.y, a1);
            }
            float r = hadd2(a0) + hadd2(a1) + __ldg(B + c);
            (&buf.x)[c & 3] = r;
            if ((c & 3) == 3)
                *reinterpret_cast<float4*>(O + (size_t)node*CH + (c - 3)) = buf;
        }
    }
}

// ---------------------------------------------------------------------------
// fused edge pass, 4 lanes/edge. All q/k/v gathers issued up-front (MLP=12),
// 2-level shfl dot reduce, ex = exp(alpha) (segment-max folded: bounded
// logits, softmax ratio invariant), den/agg via L2 reductions.
// ---------------------------------------------------------------------------
__global__ void k_edge(const void* __restrict__ ei_raw){
    const int gt  = blockIdx.x*blockDim.x + threadIdx.x;
    const int e   = gt >> 2;
    const int sub = threadIdx.x & 3;

    int src, dst;
    if (g_idx64){
        const long long* ei = (const long long*)ei_raw;
        src = (int)__ldg(ei + e);
        dst = (int)__ldg(ei + NE + e);
    } else {
        const int* ei = (const int*)ei_raw;
        src = __ldg(ei + e);
        dst = __ldg(ei + NE + e);
    }
    src = min(max(src, 0), NN-1);
    dst = min(max(dst, 0), NN-1);

    const float4* qp = reinterpret_cast<const float4*>(g_q) + (size_t)dst*16;
    const float4* kp = reinterpret_cast<const float4*>(g_k) + (size_t)src*16;
    const float4* vp = reinterpret_cast<const float4*>(g_v) + (size_t)src*16;

    float4 q0 = qp[sub],   q1 = qp[sub+4],  q2 = qp[sub+8],  q3 = qp[sub+12];
    float4 k0 = kp[sub],   k1 = kp[sub+4],  k2 = kp[sub+8],  k3 = kp[sub+12];
    float4 v0 = vp[sub],   v1 = vp[sub+4],  v2 = vp[sub+8],  v3 = vp[sub+12];

    float d = q0.x*k0.x + q0.y*k0.y + q0.z*k0.z + q0.w*k0.w
            + q1.x*k1.x + q1.y*k1.y + q1.z*k1.z + q1.w*k1.w
            + q2.x*k2.x + q2.y*k2.y + q2.z*k2.z + q2.w*k2.w
            + q3.x*k3.x + q3.y*k3.y + q3.z*k3.z + q3.w*k3.w;
    d += __shfl_xor_sync(0xffffffffu, d, 2);
    d += __shfl_xor_sync(0xffffffffu, d, 1);
    const float ex = __expf(d * 0.125f);   // 1/sqrt(64)

    if (sub == 0) atomicAdd(g_den + dst, ex);

    float* ap = g_agg + (size_t)dst*CH;
    asm volatile("red.global.add.v4.f32 [%0], {%1, %2, %3, %4};"
        :: "l"(ap + sub*4),      "f"(ex*v0.x), "f"(ex*v0.y), "f"(ex*v0.z), "f"(ex*v0.w) : "memory");
    asm volatile("red.global.add.v4.f32 [%0], {%1, %2, %3, %4};"
        :: "l"(ap + 16 + sub*4), "f"(ex*v1.x), "f"(ex*v1.y), "f"(ex*v1.z), "f"(ex*v1.w) : "memory");
    asm volatile("red.global.add.v4.f32 [%0], {%1, %2, %3, %4};"
        :: "l"(ap + 32 + sub*4), "f"(ex*v2.x), "f"(ex*v2.y), "f"(ex*v2.z), "f"(ex*v2.w) : "memory");
    asm volatile("red.global.add.v4.f32 [%0], {%1, %2, %3, %4};"
        :: "l"(ap + 48 + sub*4), "f"(ex*v3.x), "f"(ex*v3.y), "f"(ex*v3.z), "f"(ex*v3.w) : "memory");
}

// ---------------------------------------------------------------------------
// out_pre = agg/(den+1e-16) + skip ; global sum/sumsq
// ---------------------------------------------------------------------------
__global__ void k_final1(float* __restrict__ out){
    float lsum = 0.f, lsq = 0.f;
    const float4* agg4  = reinterpret_cast<const float4*>(g_agg);
    const float4* skip4 = reinterpret_cast<const float4*>(g_skip);
    float4* out4 = reinterpret_cast<float4*>(out);
    for (int i = blockIdx.x*blockDim.x + threadIdx.x; i < NN*16;
         i += gridDim.x*blockDim.x){
        float4 a = agg4[i];
        float4 s = skip4[i];
        const float inv = 1.f / (g_den[i>>4] + 1e-16f);
        float4 val;
        val.x = a.x*inv + s.x;  val.y = a.y*inv + s.y;
        val.z = a.z*inv + s.z;  val.w = a.w*inv + s.w;
        out4[i] = val;
        lsum += val.x + val.y + val.z + val.w;
        lsq  += val.x*val.x + val.y*val.y + val.z*val.z + val.w*val.w;
    }
    #pragma unroll
    for (int off=16; off>0; off>>=1){
        lsum += __shfl_xor_sync(0xffffffffu, lsum, off);
        lsq  += __shfl_xor_sync(0xffffffffu, lsq,  off);
    }
    __shared__ float s1[8], s2[8];
    const int wid = threadIdx.x >> 5;
    if ((threadIdx.x & 31) == 0){ s1[wid] = lsum; s2[wid] = lsq; }
    __syncthreads();
    if (threadIdx.x == 0){
        float ts = 0.f, tq = 0.f;
        #pragma unroll
        for (int i=0;i<8;i++){ ts += s1[i]; tq += s2[i]; }
        atomicAdd(&g_red[0], (double)ts);
        atomicAdd(&g_red[1], (double)tq);
    }
}

// ---------------------------------------------------------------------------
// graph layernorm + relu
// ---------------------------------------------------------------------------
__global__ void k_final2(float* __restrict__ out,
                         const float* __restrict__ lnw,
                         const float* __restrict__ lnb){
    const int i = blockIdx.x*blockDim.x + threadIdx.x;
    if (i >= NN*16) return;
    const double invM = 1.0 / (double)(NN*CH);
    const float mean = (float)(g_red[0]*invM);
    const float var  = (float)(g_red[1]*invM) - mean*mean;
    const float rstd = 1.f / (sqrtf(fmaxf(var, 0.f)) + 1e-5f);
    const int cb = (i & 15) * 4;
    const float4 wv = *reinterpret_cast<const float4*>(lnw + cb);
    const float4 bv = *reinterpret_cast<const float4*>(lnb + cb);
    float4 x = reinterpret_cast<float4*>(out)[i];
    float4 y;
    y.x = fmaxf((x.x - mean)*rstd*wv.x + bv.x, 0.f);
    y.y = fmaxf((x.y - mean)*rstd*wv.y + bv.y, 0.f);
    y.z = fmaxf((x.z - mean)*rstd*wv.z + bv.z, 0.f);
    y.w = fmaxf((x.w - mean)*rstd*wv.w + bv.w, 0.f);
    reinterpret_cast<float4*>(out)[i] = y;
}

// ---------------------------------------------------------------------------
extern "C" void kernel_launch(void* const* d_in, const int* in_sizes, int n_in,
                              void* d_out, int out_size){
    const float* geo = (const float*)d_in[0];
    const float* euc = (const float*)d_in[1];
    const float* Wq  = (const float*)d_in[2];
    const float* bq  = (const float*)d_in[3];
    const float* Wk  = (const float*)d_in[4];
    const float* bk  = (const float*)d_in[5];
    const float* Wv  = (const float*)d_in[6];
    const float* bv  = (const float*)d_in[7];
    const float* Ws  = (const float*)d_in[8];
    const float* bs  = (const float*)d_in[9];
    const float* lnw = (const float*)d_in[10];
    const float* lnb = (const float*)d_in[11];

    const void* ei = d_in[12];
    for (int i = 0; i < n_in; i++)
        if (in_sizes[i] == 2*NE){ ei = d_in[i]; break; }

    float* out = (float*)d_out;

    // stage weights into the constant bank (D2D async copies; capturable)
    cudaMemcpyToSymbolAsync(c_W, Wq, 16384, 0*16384, cudaMemcpyDeviceToDevice, 0);
    cudaMemcpyToSymbolAsync(c_W, Wk, 16384, 1*16384, cudaMemcpyDeviceToDevice, 0);
    cudaMemcpyToSymbolAsync(c_W, Wv, 16384, 2*16384, cudaMemcpyDeviceToDevice, 0);
    cudaMemcpyToSymbolAsync(c_W, Ws, 16384, 3*16384, cudaMemcpyDeviceToDevice, 0);

    k_zero   <<<NN*16/256, 256>>>();
    k_detect <<<1, 32>>>((const unsigned int*)ei);
    k_qkvs   <<<1563, 128>>>(geo, euc, bq, bk, bv, bs);
    k_edge   <<<NE*4/256, 256>>>(ei);
    k_final1 <<<592, 256>>>(out);
    k_final2 <<<(NN*16 + 255)/256, 256>>>(out, lnw, lnb);
}

// round 6
// speedup vs baseline: 1.9198x; 1.9198x over previous
#include <cuda_runtime.h>

#define NN 100000
#define NE 1600000
#define CH 64
#define NT 128                 // nodes per qkvs tile
#define NTILES 782             // ceil(NN/NT)

typedef unsigned long long ull;

// Scratch (device globals — no allocation allowed)
__device__ __align__(16) float g_q[NN*CH];
__device__ __align__(16) float g_k[NN*CH];
__device__ __align__(16) float g_v[NN*CH];
__device__ __align__(16) float g_skip[NN*CH];
__device__ __align__(16) float g_agg[NN*CH];
__device__ float g_den[NN];
__device__ double g_red[2];
__device__ int g_idx64;

__device__ __forceinline__ ull ffma2(ull a, ull b, ull c){
    ull d;
    asm("fma.rn.f32x2 %0, %1, %2, %3;" : "=l"(d) : "l"(a), "l"(b), "l"(c));
    return d;
}
__device__ __forceinline__ ull splat2(float f){
    ull r;
    asm("mov.b64 %0, {%1, %1};" : "=l"(r) : "f"(f));
    return r;
}
__device__ __forceinline__ void unpack2(ull a, float& lo, float& hi){
    asm("mov.b64 {%0, %1}, %2;" : "=f"(lo), "=f"(hi) : "l"(a));
}

// ---------------------------------------------------------------------------
// zero accumulators (split: also pads launch order so k_qkvs is 4th → ncu)
// ---------------------------------------------------------------------------
__global__ void k_zero_agg(){
    int i = blockIdx.x*blockDim.x + threadIdx.x;          // NN*16 float4
    reinterpret_cast<float4*>(g_agg)[i] = make_float4(0.f,0.f,0.f,0.f);
}
__global__ void k_zero_den(){
    int i = blockIdx.x*blockDim.x + threadIdx.x;
    if (i < NN/4)
        reinterpret_cast<float4*>(g_den)[i] = make_float4(0.f,0.f,0.f,0.f);
    if (i == 0){ g_red[0] = 0.0; g_red[1] = 0.0; }
}

// ---------------------------------------------------------------------------
// detect dtype of edge_index (int64 vs int32), 1 warp
// ---------------------------------------------------------------------------
__global__ void k_detect(const unsigned int* __restrict__ ei32){
    unsigned int hi = ei32[2*threadIdx.x + 1];
    unsigned int b = __ballot_sync(0xffffffffu, hi != 0u);
    if (threadIdx.x == 0) g_idx64 = (b == 0u);
}

// ---------------------------------------------------------------------------
// qkvs v5: register-tiled GEMM. Thread = (cg, ng): 4 channels x 8 nodes x
// 2 matrices = 64 fp32 accumulators (32 f32x2). Per k-step: 2 LDS.128 (x
// node-pairs) + 2 LDS.128 (w 4-channel chunks, 2 matrices) -> 32 FFMA2.
// W transposed in smem [m][kk][68-pad], x tile transposed [kk][132-pad].
// Two phases per tile: euc -> (q, skip), geo -> (k, v).
// ---------------------------------------------------------------------------
#define QKV_SMEM_BYTES ((4*64*68 + 64*132 + 256)*4)

__global__ void __launch_bounds__(256, 2) k_qkvs(
    const float* __restrict__ geo, const float* __restrict__ euc,
    const float* __restrict__ Wq, const float* __restrict__ Wk,
    const float* __restrict__ Wv, const float* __restrict__ Wsk,
    const float* __restrict__ bq, const float* __restrict__ bk,
    const float* __restrict__ bv, const float* __restrict__ bsk)
{
    extern __shared__ float sm[];
    float* w_s = sm;                       // [4][64][68]  w_s[m][kk][c]
    float* x_s = sm + 4*64*68;             // [64][132]    x_s[kk][node_local]
    float* b_s = x_s + 64*132;             // [4][64]

    const int tid = threadIdx.x;

    // stage W transposed (one-time)
    {
        const float4* Wsrc[4] = {(const float4*)Wq, (const float4*)Wk,
                                 (const float4*)Wv, (const float4*)Wsk};
        #pragma unroll
        for (int j = 0; j < 16; j++){
            int f = j*256 + tid;           // 0..4095
            int m = f >> 10, r = f & 1023;
            int c = r >> 4, kc = r & 15;
            float4 v = Wsrc[m][c*16 + kc];
            float* wb = w_s + (m*64 + kc*4)*68 + c;
            wb[0]      = v.x;
            wb[68]     = v.y;
            wb[136]    = v.z;
            wb[204]    = v.w;
        }
        if (tid < 64){
            b_s[tid]       = bq[tid];
            b_s[64 + tid]  = bk[tid];
            b_s[128 + tid] = bv[tid];
            b_s[192 + tid] = bsk[tid];
        }
    }

    const int cg = tid >> 4;               // 0..15 -> c0 = 4*cg
    const int ng = tid & 15;               // 0..15 -> n0 = 8*ng
    const int c0 = cg*4;

    #pragma unroll 1
    for (int t = blockIdx.x; t < NTILES; t += gridDim.x){
        const int base = t*NT;
        #pragma unroll 1
        for (int ph = 0; ph < 2; ph++){
            const float* X = ph ? geo : euc;
            const int mA = ph ? 1 : 0;      // k : q
            const int mB = ph ? 2 : 3;      // v : skip
            float* OA    = ph ? g_k : g_q;
            float* OB    = ph ? g_v : g_skip;

            __syncthreads();                // x_s free from previous readers
            #pragma unroll
            for (int j = 0; j < 8; j++){
                int f = j*256 + tid;        // 0..2047
                int nl = f >> 4;            // 0..127
                int kc = f & 15;
                int node = min(base + nl, NN-1);
                float4 v = *reinterpret_cast<const float4*>(
                    X + (size_t)node*CH + kc*4);
                float* xb = x_s + (kc*4)*132 + nl;
                xb[0]     = v.x;
                xb[132]   = v.y;
                xb[264]   = v.z;
                xb[396]   = v.w;
            }
            __syncthreads();

            ull acc[2][4][4];
            #pragma unroll
            for (int a = 0; a < 2; a++)
                #pragma unroll
                for (int b = 0; b < 4; b++)
                    #pragma unroll
                    for (int c = 0; c < 4; c++) acc[a][b][c] = 0ull;

            const float* wArow = w_s + mA*64*68 + c0;
            const float* wBrow = w_s + mB*64*68 + c0;
            const float* xrow  = x_s + ng*8;

            #pragma unroll 8
            for (int kk = 0; kk < 64; kk++){
                ulonglong2 xa = *reinterpret_cast<const ulonglong2*>(xrow + kk*132);
                ulonglong2 xb = *reinterpret_cast<const ulonglong2*>(xrow + kk*132 + 4);
                float4 wA = *reinterpret_cast<const float4*>(wArow + kk*68);
                float4 wB = *reinterpret_cast<const float4*>(wBrow + kk*68);
                #pragma unroll
                for (int ci = 0; ci < 4; ci++){
                    ull sA = splat2((&wA.x)[ci]);
                    acc[0][ci][0] = ffma2(xa.x, sA, acc[0][ci][0]);
                    acc[0][ci][1] = ffma2(xa.y, sA, acc[0][ci][1]);
                    acc[0][ci][2] = ffma2(xb.x, sA, acc[0][ci][2]);
                    acc[0][ci][3] = ffma2(xb.y, sA, acc[0][ci][3]);
                }
                #pragma unroll
                for (int ci = 0; ci < 4; ci++){
                    ull sB = splat2((&wB.x)[ci]);
                    acc[1][ci][0] = ffma2(xa.x, sB, acc[1][ci][0]);
                    acc[1][ci][1] = ffma2(xa.y, sB, acc[1][ci][1]);
                    acc[1][ci][2] = ffma2(xb.x, sB, acc[1][ci][2]);
                    acc[1][ci][3] = ffma2(xb.y, sB, acc[1][ci][3]);
                }
            }

            // epilogue: add bias, store float4 per (node, matrix)
            float biasA[4], biasB[4];
            #pragma unroll
            for (int ci = 0; ci < 4; ci++){
                biasA[ci] = b_s[mA*64 + c0 + ci];
                biasB[ci] = b_s[mB*64 + c0 + ci];
            }
            const int n0 = base + ng*8;
            #pragma unroll
            for (int np = 0; np < 4; np++){
                float4 loA, hiA, loB, hiB;
                #pragma unroll
                for (int ci = 0; ci < 4; ci++){
                    float lo, hi;
                    unpack2(acc[0][ci][np], lo, hi);
                    (&loA.x)[ci] = lo + biasA[ci];
                    (&hiA.x)[ci] = hi + biasA[ci];
                    unpack2(acc[1][ci][np], lo, hi);
                    (&loB.x)[ci] = lo + biasB[ci];
                    (&hiB.x)[ci] = hi + biasB[ci];
                }
                const int nlo = n0 + 2*np, nhi = n0 + 2*np + 1;
                if (nlo < NN){
                    *reinterpret_cast<float4*>(OA + (size_t)nlo*CH + c0) = loA;
                    *reinterpret_cast<float4*>(OB + (size_t)nlo*CH + c0) = loB;
                }
                if (nhi < NN){
                    *reinterpret_cast<float4*>(OA + (size_t)nhi*CH + c0) = hiA;
                    *reinterpret_cast<float4*>(OB + (size_t)nhi*CH + c0) = hiB;
                }
            }
        }
    }
}

// ---------------------------------------------------------------------------
// fused edge pass, 4 lanes/edge (unchanged — measured 141us, L1-bound)
// ---------------------------------------------------------------------------
__global__ void k_edge(const void* __restrict__ ei_raw){
    const int gt  = blockIdx.x*blockDim.x + threadIdx.x;
    const int e   = gt >> 2;
    const int sub = threadIdx.x & 3;

    int src, dst;
    if (g_idx64){
        const long long* ei = (const long long*)ei_raw;
        src = (int)__ldg(ei + e);
        dst = (int)__ldg(ei + NE + e);
    } else {
        const int* ei = (const int*)ei_raw;
        src = __ldg(ei + e);
        dst = __ldg(ei + NE + e);
    }
    src = min(max(src, 0), NN-1);
    dst = min(max(dst, 0), NN-1);

    const float4* qp = reinterpret_cast<const float4*>(g_q) + (size_t)dst*16;
    const float4* kp = reinterpret_cast<const float4*>(g_k) + (size_t)src*16;
    const float4* vp = reinterpret_cast<const float4*>(g_v) + (size_t)src*16;

    float4 q0 = qp[sub],   q1 = qp[sub+4],  q2 = qp[sub+8],  q3 = qp[sub+12];
    float4 k0 = kp[sub],   k1 = kp[sub+4],  k2 = kp[sub+8],  k3 = kp[sub+12];
    float4 v0 = vp[sub],   v1 = vp[sub+4],  v2 = vp[sub+8],  v3 = vp[sub+12];

    float d = q0.x*k0.x + q0.y*k0.y + q0.z*k0.z + q0.w*k0.w
            + q1.x*k1.x + q1.y*k1.y + q1.z*k1.z + q1.w*k1.w
            + q2.x*k2.x + q2.y*k2.y + q2.z*k2.z + q2.w*k2.w
            + q3.x*k3.x + q3.y*k3.y + q3.z*k3.z + q3.w*k3.w;
    d += __shfl_xor_sync(0xffffffffu, d, 2);
    d += __shfl_xor_sync(0xffffffffu, d, 1);
    const float ex = __expf(d * 0.125f);   // 1/sqrt(64)

    if (sub == 0) atomicAdd(g_den + dst, ex);

    float* ap = g_agg + (size_t)dst*CH;
    asm volatile("red.global.add.v4.f32 [%0], {%1, %2, %3, %4};"
        :: "l"(ap + sub*4),      "f"(ex*v0.x), "f"(ex*v0.y), "f"(ex*v0.z), "f"(ex*v0.w) : "memory");
    asm volatile("red.global.add.v4.f32 [%0], {%1, %2, %3, %4};"
        :: "l"(ap + 16 + sub*4), "f"(ex*v1.x), "f"(ex*v1.y), "f"(ex*v1.z), "f"(ex*v1.w) : "memory");
    asm volatile("red.global.add.v4.f32 [%0], {%1, %2, %3, %4};"
        :: "l"(ap + 32 + sub*4), "f"(ex*v2.x), "f"(ex*v2.y), "f"(ex*v2.z), "f"(ex*v2.w) : "memory");
    asm volatile("red.global.add.v4.f32 [%0], {%1, %2, %3, %4};"
        :: "l"(ap + 48 + sub*4), "f"(ex*v3.x), "f"(ex*v3.y), "f"(ex*v3.z), "f"(ex*v3.w) : "memory");
}

// ---------------------------------------------------------------------------
// out_pre = agg/(den+1e-16) + skip ; global sum/sumsq
// ---------------------------------------------------------------------------
__global__ void k_final1(float* __restrict__ out){
    float lsum = 0.f, lsq = 0.f;
    const float4* agg4  = reinterpret_cast<const float4*>(g_agg);
    const float4* skip4 = reinterpret_cast<const float4*>(g_skip);
    float4* out4 = reinterpret_cast<float4*>(out);
    for (int i = blockIdx.x*blockDim.x + threadIdx.x; i < NN*16;
         i += gridDim.x*blockDim.x){
        float4 a = agg4[i];
        float4 s = skip4[i];
        const float inv = 1.f / (g_den[i>>4] + 1e-16f);
        float4 val;
        val.x = a.x*inv + s.x;  val.y = a.y*inv + s.y;
        val.z = a.z*inv + s.z;  val.w = a.w*inv + s.w;
        out4[i] = val;
        lsum += val.x + val.y + val.z + val.w;
        lsq  += val.x*val.x + val.y*val.y + val.z*val.z + val.w*val.w;
    }
    #pragma unroll
    for (int off=16; off>0; off>>=1){
        lsum += __shfl_xor_sync(0xffffffffu, lsum, off);
        lsq  += __shfl_xor_sync(0xffffffffu, lsq,  off);
    }
    __shared__ float s1[8], s2[8];
    const int wid = threadIdx.x >> 5;
    if ((threadIdx.x & 31) == 0){ s1[wid] = lsum; s2[wid] = lsq; }
    __syncthreads();
    if (threadIdx.x == 0){
        float ts = 0.f, tq = 0.f;
        #pragma unroll
        for (int i=0;i<8;i++){ ts += s1[i]; tq += s2[i]; }
        atomicAdd(&g_red[0], (double)ts);
        atomicAdd(&g_red[1], (double)tq);
    }
}

// ---------------------------------------------------------------------------
// graph layernorm + relu
// ---------------------------------------------------------------------------
__global__ void k_final2(float* __restrict__ out,
                         const float* __restrict__ lnw,
                         const float* __restrict__ lnb){
    const int i = blockIdx.x*blockDim.x + threadIdx.x;
    if (i >= NN*16) return;
    const double invM = 1.0 / (double)(NN*CH);
    const float mean = (float)(g_red[0]*invM);
    const float var  = (float)(g_red[1]*invM) - mean*mean;
    const float rstd = 1.f / (sqrtf(fmaxf(var, 0.f)) + 1e-5f);
    const int cb = (i & 15) * 4;
    const float4 wv = *reinterpret_cast<const float4*>(lnw + cb);
    const float4 bv = *reinterpret_cast<const float4*>(lnb + cb);
    float4 x = reinterpret_cast<float4*>(out)[i];
    float4 y;
    y.x = fmaxf((x.x - mean)*rstd*wv.x + bv.x, 0.f);
    y.y = fmaxf((x.y - mean)*rstd*wv.y + bv.y, 0.f);
    y.z = fmaxf((x.z - mean)*rstd*wv.z + bv.z, 0.f);
    y.w = fmaxf((x.w - mean)*rstd*wv.w + bv.w, 0.f);
    reinterpret_cast<float4*>(out)[i] = y;
}

// ---------------------------------------------------------------------------
extern "C" void kernel_launch(void* const* d_in, const int* in_sizes, int n_in,
                              void* d_out, int out_size){
    const float* geo = (const float*)d_in[0];
    const float* euc = (const float*)d_in[1];
    const float* Wq  = (const float*)d_in[2];
    const float* bq  = (const float*)d_in[3];
    const float* Wk  = (const float*)d_in[4];
    const float* bk  = (const float*)d_in[5];
    const float* Wv  = (const float*)d_in[6];
    const float* bv  = (const float*)d_in[7];
    const float* Ws  = (const float*)d_in[8];
    const float* bs  = (const float*)d_in[9];
    const float* lnw = (const float*)d_in[10];
    const float* lnb = (const float*)d_in[11];

    const void* ei = d_in[12];
    for (int i = 0; i < n_in; i++)
        if (in_sizes[i] == 2*NE){ ei = d_in[i]; break; }

    float* out = (float*)d_out;

    cudaFuncSetAttribute(k_qkvs, cudaFuncAttributeMaxDynamicSharedMemorySize,
                         QKV_SMEM_BYTES);

    k_zero_agg<<<NN*16/256, 256>>>();
    k_zero_den<<<(NN/4 + 255)/256, 256>>>();
    k_detect  <<<1, 32>>>((const unsigned int*)ei);
    k_qkvs    <<<296, 256, QKV_SMEM_BYTES>>>(geo, euc, Wq, Wk, Wv, Ws,
                                             bq, bk, bv, bs);
    k_edge    <<<NE*4/256, 256>>>(ei);
    k_final1  <<<592, 256>>>(out);
    k_final2  <<<(NN*16 + 255)/256, 256>>>(out, lnw, lnb);
}

// round 7
// speedup vs baseline: 1.9560x; 1.0189x over previous
#include <cuda_runtime.h>

#define NN 100000
#define NE 1600000
#define CH 64
#define NT 128                 // nodes per qkvs tile
#define NTILES 782             // ceil(NN/NT)
#define WMAT 4416              // floats per matrix in w_s (64*68 + skew pad)
#define XSZ  8512              // x tile floats (64*132 + skew pad)

typedef unsigned long long ull;

// Scratch (device globals — no allocation allowed)
__device__ __align__(16) float g_q[NN*CH];
__device__ __align__(16) float g_k[NN*CH];
__device__ __align__(16) float g_v[NN*CH];
__device__ __align__(16) float g_skip[NN*CH];
__device__ __align__(16) float g_agg[NN*CH];
__device__ float g_den[NN];
__device__ double g_red[2];
__device__ int g_idx64;

__device__ __forceinline__ ull ffma2(ull a, ull b, ull c){
    ull d;
    asm("fma.rn.f32x2 %0, %1, %2, %3;" : "=l"(d) : "l"(a), "l"(b), "l"(c));
    return d;
}
__device__ __forceinline__ ull splat2(float f){
    ull r;
    asm("mov.b64 %0, {%1, %1};" : "=l"(r) : "f"(f));
    return r;
}
__device__ __forceinline__ void unpack2(ull a, float& lo, float& hi){
    asm("mov.b64 {%0, %1}, %2;" : "=f"(lo), "=f"(hi) : "l"(a));
}

// ---------------------------------------------------------------------------
// zero accumulators + reduction cells
// ---------------------------------------------------------------------------
__global__ void k_zero(){
    int i = blockIdx.x*blockDim.x + threadIdx.x;          // NN*16 float4
    reinterpret_cast<float4*>(g_agg)[i] = make_float4(0.f,0.f,0.f,0.f);
    if (i < NN/4)
        reinterpret_cast<float4*>(g_den)[i] = make_float4(0.f,0.f,0.f,0.f);
    if (i == 0){ g_red[0] = 0.0; g_red[1] = 0.0; }
}

// ---------------------------------------------------------------------------
// detect dtype of edge_index (int64 vs int32), 1 warp
// ---------------------------------------------------------------------------
__global__ void k_detect(const unsigned int* __restrict__ ei32){
    unsigned int hi = ei32[2*threadIdx.x + 1];
    unsigned int b = __ballot_sync(0xffffffffu, hi != 0u);
    if (threadIdx.x == 0) g_idx64 = (b == 0u);
}

// ---------------------------------------------------------------------------
// qkvs v6: register-tiled GEMM (4ch x 8node x 2mat = 64 fp32 acc / thread),
// with SKEWED smem layouts: row kk lives at kk*stride + (kk>>2)*4, which
// turns the 8-way staging-STS bank conflicts (528|272 ≡ 16 mod 32) into
// 2-way (532|276 ≡ 20 mod 32) while keeping 16B alignment for LDS.128.
// ---------------------------------------------------------------------------
#define QKV_SMEM_BYTES ((4*WMAT + XSZ + 256)*4)

__global__ void __launch_bounds__(256, 2) k_qkvs(
    const float* __restrict__ geo, const float* __restrict__ euc,
    const float* __restrict__ Wq, const float* __restrict__ Wk,
    const float* __restrict__ Wv, const float* __restrict__ Wsk,
    const float* __restrict__ bq, const float* __restrict__ bk,
    const float* __restrict__ bv, const float* __restrict__ bsk)
{
    extern __shared__ float sm[];
    float* w_s = sm;                       // [4][WMAT]  w[m][kk][c] skewed
    float* x_s = sm + 4*WMAT;              // [XSZ]      x[kk][nl]   skewed
    float* b_s = x_s + XSZ;                // [4][64]

    const int tid = threadIdx.x;

    // stage W transposed+skewed (one-time)
    {
        const float4* Wsrc[4] = {(const float4*)Wq, (const float4*)Wk,
                                 (const float4*)Wv, (const float4*)Wsk};
        #pragma unroll
        for (int j = 0; j < 16; j++){
            int f = j*256 + tid;           // 0..4095
            int m = f >> 10, r = f & 1023;
            int c = r >> 4, kc = r & 15;
            float4 v = Wsrc[m][c*16 + kc];
            float* wb = w_s + m*WMAT + 276*kc + c;   // WOFF(4kc)+c
            wb[0]   = v.x;
            wb[68]  = v.y;
            wb[136] = v.z;
            wb[204] = v.w;
        }
        if (tid < 64){
            b_s[tid]       = bq[tid];
            b_s[64 + tid]  = bk[tid];
            b_s[128 + tid] = bv[tid];
            b_s[192 + tid] = bsk[tid];
        }
    }

    const int cg = tid >> 4;               // 0..15 -> c0 = 4*cg
    const int ng = tid & 15;               // 0..15 -> n0 = 8*ng
    const int c0 = cg*4;

    #pragma unroll 1
    for (int t = blockIdx.x; t < NTILES; t += gridDim.x){
        const int base = t*NT;
        #pragma unroll 1
        for (int ph = 0; ph < 2; ph++){
            const float* X = ph ? geo : euc;
            const int mA = ph ? 1 : 0;      // k : q
            const int mB = ph ? 2 : 3;      // v : skip
            float* OA    = ph ? g_k : g_q;
            float* OB    = ph ? g_v : g_skip;

            __syncthreads();                // x_s free from previous readers
            #pragma unroll
            for (int j = 0; j < 8; j++){
                int f = j*256 + tid;        // 0..2047
                int nl = f >> 4;            // 0..127
                int kc = f & 15;
                int node = min(base + nl, NN-1);
                float4 v = *reinterpret_cast<const float4*>(
                    X + (size_t)node*CH + kc*4);
                float* xb = x_s + 532*kc + nl;       // XOFF(4kc)+nl
                xb[0]   = v.x;
                xb[132] = v.y;
                xb[264] = v.z;
                xb[396] = v.w;
            }
            __syncthreads();

            ull acc[2][4][4];
            #pragma unroll
            for (int a = 0; a < 2; a++)
                #pragma unroll
                for (int b = 0; b < 4; b++)
                    #pragma unroll
                    for (int c = 0; c < 4; c++) acc[a][b][c] = 0ull;

            const float* wArow = w_s + mA*WMAT + c0;
            const float* wBrow = w_s + mB*WMAT + c0;
            const float* xrow  = x_s + ng*8;

            #pragma unroll 8
            for (int kk = 0; kk < 64; kk++){
                const int xo = kk*132 + (kk>>2)*4;
                const int wo = kk*68  + (kk>>2)*4;
                ulonglong2 xa = *reinterpret_cast<const ulonglong2*>(xrow + xo);
                ulonglong2 xb = *reinterpret_cast<const ulonglong2*>(xrow + xo + 4);
                float4 wA = *reinterpret_cast<const float4*>(wArow + wo);
                float4 wB = *reinterpret_cast<const float4*>(wBrow + wo);
                #pragma unroll
                for (int ci = 0; ci < 4; ci++){
                    ull sA = splat2((&wA.x)[ci]);
                    acc[0][ci][0] = ffma2(xa.x, sA, acc[0][ci][0]);
                    acc[0][ci][1] = ffma2(xa.y, sA, acc[0][ci][1]);
                    acc[0][ci][2] = ffma2(xb.x, sA, acc[0][ci][2]);
                    acc[0][ci][3] = ffma2(xb.y, sA, acc[0][ci][3]);
                }
                #pragma unroll
                for (int ci = 0; ci < 4; ci++){
                    ull sB = splat2((&wB.x)[ci]);
                    acc[1][ci][0] = ffma2(xa.x, sB, acc[1][ci][0]);
                    acc[1][ci][1] = ffma2(xa.y, sB, acc[1][ci][1]);
                    acc[1][ci][2] = ffma2(xb.x, sB, acc[1][ci][2]);
                    acc[1][ci][3] = ffma2(xb.y, sB, acc[1][ci][3]);
                }
            }

            // epilogue: add bias, store float4 per (node, matrix)
            float biasA[4], biasB[4];
            #pragma unroll
            for (int ci = 0; ci < 4; ci++){
                biasA[ci] = b_s[mA*64 + c0 + ci];
                biasB[ci] = b_s[mB*64 + c0 + ci];
            }
            const int n0 = base + ng*8;
            #pragma unroll
            for (int np = 0; np < 4; np++){
                float4 loA, hiA, loB, hiB;
                #pragma unroll
                for (int ci = 0; ci < 4; ci++){
                    float lo, hi;
                    unpack2(acc[0][ci][np], lo, hi);
                    (&loA.x)[ci] = lo + biasA[ci];
                    (&hiA.x)[ci] = hi + biasA[ci];
                    unpack2(acc[1][ci][np], lo, hi);
                    (&loB.x)[ci] = lo + biasB[ci];
                    (&hiB.x)[ci] = hi + biasB[ci];
                }
                const int nlo = n0 + 2*np, nhi = n0 + 2*np + 1;
                if (nlo < NN){
                    *reinterpret_cast<float4*>(OA + (size_t)nlo*CH + c0) = loA;
                    *reinterpret_cast<float4*>(OB + (size_t)nlo*CH + c0) = loB;
                }
                if (nhi < NN){
                    *reinterpret_cast<float4*>(OA + (size_t)nhi*CH + c0) = hiA;
                    *reinterpret_cast<float4*>(OB + (size_t)nhi*CH + c0) = hiB;
                }
            }
        }
    }
}

// ---------------------------------------------------------------------------
// fused edge pass, 8 lanes/edge: every LDG.128/RED.128 covers 4 edges x
// 128B = full cache lines (halves L1tex wavefronts vs 4-lane). 6 gathers
// up-front (MLP=6), 3-level shfl dot, exp w/o segment-max (bounded logits).
// ---------------------------------------------------------------------------
__global__ void k_edge(const void* __restrict__ ei_raw){
    const int gt  = blockIdx.x*blockDim.x + threadIdx.x;
    const int e   = gt >> 3;
    const int sub = threadIdx.x & 7;

    int src, dst;
    if (g_idx64){
        const long long* ei = (const long long*)ei_raw;
        src = (int)__ldg(ei + e);
        dst = (int)__ldg(ei + NE + e);
    } else {
        const int* ei = (const int*)ei_raw;
        src = __ldg(ei + e);
        dst = __ldg(ei + NE + e);
    }
    src = min(max(src, 0), NN-1);
    dst = min(max(dst, 0), NN-1);

    const float4* qp = reinterpret_cast<const float4*>(g_q) + (size_t)dst*16 + sub*2;
    const float4* kp = reinterpret_cast<const float4*>(g_k) + (size_t)src*16 + sub*2;
    const float4* vp = reinterpret_cast<const float4*>(g_v) + (size_t)src*16 + sub*2;

    float4 q0 = qp[0], q1 = qp[1];
    float4 k0 = kp[0], k1 = kp[1];
    float4 v0 = vp[0], v1 = vp[1];

    float d = q0.x*k0.x + q0.y*k0.y + q0.z*k0.z + q0.w*k0.w
            + q1.x*k1.x + q1.y*k1.y + q1.z*k1.z + q1.w*k1.w;
    d += __shfl_xor_sync(0xffffffffu, d, 4);
    d += __shfl_xor_sync(0xffffffffu, d, 2);
    d += __shfl_xor_sync(0xffffffffu, d, 1);
    const float ex = __expf(d * 0.125f);   // 1/sqrt(64)

    if (sub == 0) atomicAdd(g_den + dst, ex);

    float* ap = g_agg + (size_t)dst*CH + sub*8;
    asm volatile("red.global.add.v4.f32 [%0], {%1, %2, %3, %4};"
        :: "l"(ap),     "f"(ex*v0.x), "f"(ex*v0.y), "f"(ex*v0.z), "f"(ex*v0.w) : "memory");
    asm volatile("red.global.add.v4.f32 [%0], {%1, %2, %3, %4};"
        :: "l"(ap + 4), "f"(ex*v1.x), "f"(ex*v1.y), "f"(ex*v1.z), "f"(ex*v1.w) : "memory");
}

// ---------------------------------------------------------------------------
// out_pre = agg/(den+1e-16) + skip ; global sum/sumsq
// ---------------------------------------------------------------------------
__global__ void k_final1(float* __restrict__ out){
    float lsum = 0.f, lsq = 0.f;
    const float4* agg4  = reinterpret_cast<const float4*>(g_agg);
    const float4* skip4 = reinterpret_cast<const float4*>(g_skip);
    float4* out4 = reinterpret_cast<float4*>(out);
    for (int i = blockIdx.x*blockDim.x + threadIdx.x; i < NN*16;
         i += gridDim.x*blockDim.x){
        float4 a = agg4[i];
        float4 s = skip4[i];
        const float inv = 1.f / (g_den[i>>4] + 1e-16f);
        float4 val;
        val.x = a.x*inv + s.x;  val.y = a.y*inv + s.y;
        val.z = a.z*inv + s.z;  val.w = a.w*inv + s.w;
        out4[i] = val;
        lsum += val.x + val.y + val.z + val.w;
        lsq  += val.x*val.x + val.y*val.y + val.z*val.z + val.w*val.w;
    }
    #pragma unroll
    for (int off=16; off>0; off>>=1){
        lsum += __shfl_xor_sync(0xffffffffu, lsum, off);
        lsq  += __shfl_xor_sync(0xffffffffu, lsq,  off);
    }
    __shared__ float s1[8], s2[8];
    const int wid = threadIdx.x >> 5;
    if ((threadIdx.x & 31) == 0){ s1[wid] = lsum; s2[wid] = lsq; }
    __syncthreads();
    if (threadIdx.x == 0){
        float ts = 0.f, tq = 0.f;
        #pragma unroll
        for (int i=0;i<8;i++){ ts += s1[i]; tq += s2[i]; }
        atomicAdd(&g_red[0], (double)ts);
        atomicAdd(&g_red[1], (double)tq);
    }
}

// ---------------------------------------------------------------------------
// graph layernorm + relu
// ---------------------------------------------------------------------------
__global__ void k_final2(float* __restrict__ out,
                         const float* __restrict__ lnw,
                         const float* __restrict__ lnb){
    const int i = blockIdx.x*blockDim.x + threadIdx.x;
    if (i >= NN*16) return;
    const double invM = 1.0 / (double)(NN*CH);
    const float mean = (float)(g_red[0]*invM);
    const float var  = (float)(g_red[1]*invM) - mean*mean;
    const float rstd = 1.f / (sqrtf(fmaxf(var, 0.f)) + 1e-5f);
    const int cb = (i & 15) * 4;
    const float4 wv = *reinterpret_cast<const float4*>(lnw + cb);
    const float4 bv = *reinterpret_cast<const float4*>(lnb + cb);
    float4 x = reinterpret_cast<float4*>(out)[i];
    float4 y;
    y.x = fmaxf((x.x - mean)*rstd*wv.x + bv.x, 0.f);
    y.y = fmaxf((x.y - mean)*rstd*wv.y + bv.y, 0.f);
    y.z = fmaxf((x.z - mean)*rstd*wv.z + bv.z, 0.f);
    y.w = fmaxf((x.w - mean)*rstd*wv.w + bv.w, 0.f);
    reinterpret_cast<float4*>(out)[i] = y;
}

// ---------------------------------------------------------------------------
extern "C" void kernel_launch(void* const* d_in, const int* in_sizes, int n_in,
                              void* d_out, int out_size){
    const float* geo = (const float*)d_in[0];
    const float* euc = (const float*)d_in[1];
    const float* Wq  = (const float*)d_in[2];
    const float* bq  = (const float*)d_in[3];
    const float* Wk  = (const float*)d_in[4];
    const float* bk  = (const float*)d_in[5];
    const float* Wv  = (const float*)d_in[6];
    const float* bv  = (const float*)d_in[7];
    const float* Ws  = (const float*)d_in[8];
    const float* bs  = (const float*)d_in[9];
    const float* lnw = (const float*)d_in[10];
    const float* lnb = (const float*)d_in[11];

    const void* ei = d_in[12];
    for (int i = 0; i < n_in; i++)
        if (in_sizes[i] == 2*NE){ ei = d_in[i]; break; }

    float* out = (float*)d_out;

    cudaFuncSetAttribute(k_qkvs, cudaFuncAttributeMaxDynamicSharedMemorySize,
                         QKV_SMEM_BYTES);

    k_zero   <<<NN*16/256, 256>>>();
    k_detect <<<1, 32>>>((const unsigned int*)ei);
    k_qkvs   <<<296, 256, QKV_SMEM_BYTES>>>(geo, euc, Wq, Wk, Wv, Ws,
                                            bq, bk, bv, bs);
    k_edge   <<<NE*8/256, 256>>>(ei);
    k_final1 <<<592, 256>>>(out);
    k_final2 <<<(NN*16 + 255)/256, 256>>>(out, lnw, lnb);
}

// round 8
// speedup vs baseline: 2.1167x; 1.0822x over previous
#include <cuda_runtime.h>
#include <cuda_fp16.h>

#define NN 100000
#define NE 1600000
#define CH 64
#define NT 128                 // nodes per qkvs tile
#define NTILES 782             // ceil(NN/NT)
#define WMAT 4416              // floats per matrix in w_s (64*68 + skew pad)
#define XSZ  8512              // x tile floats (64*132 + skew pad)

typedef unsigned long long ull;

// Scratch (device globals — no allocation allowed)
__device__ __align__(16) __half g_qh[NN*CH];   // fp16 q
__device__ __align__(16) __half g_kh[NN*CH];   // fp16 k
__device__ __align__(16) float g_v[NN*CH];
__device__ __align__(16) float g_skip[NN*CH];
__device__ __align__(16) float g_agg[NN*CH];
__device__ float g_den[NN];
__device__ double g_red[2];
__device__ int g_idx64;

__device__ __forceinline__ ull ffma2(ull a, ull b, ull c){
    ull d;
    asm("fma.rn.f32x2 %0, %1, %2, %3;" : "=l"(d) : "l"(a), "l"(b), "l"(c));
    return d;
}
__device__ __forceinline__ ull splat2(float f){
    ull r;
    asm("mov.b64 %0, {%1, %1};" : "=l"(r) : "f"(f));
    return r;
}
__device__ __forceinline__ void unpack2(ull a, float& lo, float& hi){
    asm("mov.b64 {%0, %1}, %2;" : "=f"(lo), "=f"(hi) : "l"(a));
}

// ---------------------------------------------------------------------------
// zero accumulators + reduction cells
// ---------------------------------------------------------------------------
__global__ void k_zero(){
    int i = blockIdx.x*blockDim.x + threadIdx.x;          // NN*16 float4
    reinterpret_cast<float4*>(g_agg)[i] = make_float4(0.f,0.f,0.f,0.f);
    if (i < NN/4)
        reinterpret_cast<float4*>(g_den)[i] = make_float4(0.f,0.f,0.f,0.f);
    if (i == 0){ g_red[0] = 0.0; g_red[1] = 0.0; }
}

// ---------------------------------------------------------------------------
// detect dtype of edge_index (int64 vs int32), 1 warp
// ---------------------------------------------------------------------------
__global__ void k_detect(const unsigned int* __restrict__ ei32){
    unsigned int hi = ei32[2*threadIdx.x + 1];
    unsigned int b = __ballot_sync(0xffffffffu, hi != 0u);
    if (threadIdx.x == 0) g_idx64 = (b == 0u);
}

// ---------------------------------------------------------------------------
// qkvs v7: register-tiled GEMM (4ch x 8node x 2mat = 64 fp32 acc / thread),
// skewed smem (STS conflicts 8-way -> 2-way). Output A (q or k) stored fp16,
// output B (skip or v) stored fp32.
// ---------------------------------------------------------------------------
#define QKV_SMEM_BYTES ((4*WMAT + XSZ + 256)*4)

__global__ void __launch_bounds__(256, 2) k_qkvs(
    const float* __restrict__ geo, const float* __restrict__ euc,
    const float* __restrict__ Wq, const float* __restrict__ Wk,
    const float* __restrict__ Wv, const float* __restrict__ Wsk,
    const float* __restrict__ bq, const float* __restrict__ bk,
    const float* __restrict__ bv, const float* __restrict__ bsk)
{
    extern __shared__ float sm[];
    float* w_s = sm;                       // [4][WMAT]  w[m][kk][c] skewed
    float* x_s = sm + 4*WMAT;              // [XSZ]      x[kk][nl]   skewed
    float* b_s = x_s + XSZ;                // [4][64]

    const int tid = threadIdx.x;

    // stage W transposed+skewed (one-time)
    {
        const float4* Wsrc[4] = {(const float4*)Wq, (const float4*)Wk,
                                 (const float4*)Wv, (const float4*)Wsk};
        #pragma unroll
        for (int j = 0; j < 16; j++){
            int f = j*256 + tid;           // 0..4095
            int m = f >> 10, r = f & 1023;
            int c = r >> 4, kc = r & 15;
            float4 v = Wsrc[m][c*16 + kc];
            float* wb = w_s + m*WMAT + 276*kc + c;
            wb[0]   = v.x;
            wb[68]  = v.y;
            wb[136] = v.z;
            wb[204] = v.w;
        }
        if (tid < 64){
            b_s[tid]       = bq[tid];
            b_s[64 + tid]  = bk[tid];
            b_s[128 + tid] = bv[tid];
            b_s[192 + tid] = bsk[tid];
        }
    }

    const int cg = tid >> 4;               // 0..15 -> c0 = 4*cg
    const int ng = tid & 15;               // 0..15 -> n0 = 8*ng
    const int c0 = cg*4;

    #pragma unroll 1
    for (int t = blockIdx.x; t < NTILES; t += gridDim.x){
        const int base = t*NT;
        #pragma unroll 1
        for (int ph = 0; ph < 2; ph++){
            const float* X = ph ? geo : euc;
            const int mA = ph ? 1 : 0;      // k : q   (fp16 out)
            const int mB = ph ? 2 : 3;      // v : skip (fp32 out)
            __half* OA   = ph ? g_kh : g_qh;
            float*  OB   = ph ? g_v  : g_skip;

            __syncthreads();                // x_s free from previous readers
            #pragma unroll
            for (int j = 0; j < 8; j++){
                int f = j*256 + tid;        // 0..2047
                int nl = f >> 4;            // 0..127
                int kc = f & 15;
                int node = min(base + nl, NN-1);
                float4 v = *reinterpret_cast<const float4*>(
                    X + (size_t)node*CH + kc*4);
                float* xb = x_s + 532*kc + nl;
                xb[0]   = v.x;
                xb[132] = v.y;
                xb[264] = v.z;
                xb[396] = v.w;
            }
            __syncthreads();

            ull acc[2][4][4];
            #pragma unroll
            for (int a = 0; a < 2; a++)
                #pragma unroll
                for (int b = 0; b < 4; b++)
                    #pragma unroll
                    for (int c = 0; c < 4; c++) acc[a][b][c] = 0ull;

            const float* wArow = w_s + mA*WMAT + c0;
            const float* wBrow = w_s + mB*WMAT + c0;
            const float* xrow  = x_s + ng*8;

            #pragma unroll 8
            for (int kk = 0; kk < 64; kk++){
                const int xo = kk*132 + (kk>>2)*4;
                const int wo = kk*68  + (kk>>2)*4;
                ulonglong2 xa = *reinterpret_cast<const ulonglong2*>(xrow + xo);
                ulonglong2 xb = *reinterpret_cast<const ulonglong2*>(xrow + xo + 4);
                float4 wA = *reinterpret_cast<const float4*>(wArow + wo);
                float4 wB = *reinterpret_cast<const float4*>(wBrow + wo);
                #pragma unroll
                for (int ci = 0; ci < 4; ci++){
                    ull sA = splat2((&wA.x)[ci]);
                    acc[0][ci][0] = ffma2(xa.x, sA, acc[0][ci][0]);
                    acc[0][ci][1] = ffma2(xa.y, sA, acc[0][ci][1]);
                    acc[0][ci][2] = ffma2(xb.x, sA, acc[0][ci][2]);
                    acc[0][ci][3] = ffma2(xb.y, sA, acc[0][ci][3]);
                }
                #pragma unroll
                for (int ci = 0; ci < 4; ci++){
                    ull sB = splat2((&wB.x)[ci]);
                    acc[1][ci][0] = ffma2(xa.x, sB, acc[1][ci][0]);
                    acc[1][ci][1] = ffma2(xa.y, sB, acc[1][ci][1]);
                    acc[1][ci][2] = ffma2(xb.x, sB, acc[1][ci][2]);
                    acc[1][ci][3] = ffma2(xb.y, sB, acc[1][ci][3]);
                }
            }

            // epilogue: bias; A -> fp16 (8B store), B -> fp32 (16B store)
            float biasA[4], biasB[4];
            #pragma unroll
            for (int ci = 0; ci < 4; ci++){
                biasA[ci] = b_s[mA*64 + c0 + ci];
                biasB[ci] = b_s[mB*64 + c0 + ci];
            }
            const int n0 = base + ng*8;
            #pragma unroll
            for (int np = 0; np < 4; np++){
                float4 loA, hiA, loB, hiB;
                #pragma unroll
                for (int ci = 0; ci < 4; ci++){
                    float lo, hi;
                    unpack2(acc[0][ci][np], lo, hi);
                    (&loA.x)[ci] = lo + biasA[ci];
                    (&hiA.x)[ci] = hi + biasA[ci];
                    unpack2(acc[1][ci][np], lo, hi);
                    (&loB.x)[ci] = lo + biasB[ci];
                    (&hiB.x)[ci] = hi + biasB[ci];
                }
                const int nlo = n0 + 2*np, nhi = n0 + 2*np + 1;
                if (nlo < NN){
                    __half2 a01 = __floats2half2_rn(loA.x, loA.y);
                    __half2 a23 = __floats2half2_rn(loA.z, loA.w);
                    uint2 u; u.x = *reinterpret_cast<unsigned*>(&a01);
                             u.y = *reinterpret_cast<unsigned*>(&a23);
                    *reinterpret_cast<uint2*>(OA + (size_t)nlo*CH + c0) = u;
                    *reinterpret_cast<float4*>(OB + (size_t)nlo*CH + c0) = loB;
                }
                if (nhi < NN){
                    __half2 a01 = __floats2half2_rn(hiA.x, hiA.y);
                    __half2 a23 = __floats2half2_rn(hiA.z, hiA.w);
                    uint2 u; u.x = *reinterpret_cast<unsigned*>(&a01);
                             u.y = *reinterpret_cast<unsigned*>(&a23);
                    *reinterpret_cast<uint2*>(OA + (size_t)nhi*CH + c0) = u;
                    *reinterpret_cast<float4*>(OB + (size_t)nhi*CH + c0) = hiB;
                }
            }
        }
    }
}

// ---------------------------------------------------------------------------
// fused edge pass, 8 lanes/edge, fp16 q/k (128B rows -> one LDG.128 each).
// Per edge L2 bytes: 128(q)+128(k)+256(v)+256(red) vs 1280 before.
// ---------------------------------------------------------------------------
__global__ void k_edge(const void* __restrict__ ei_raw){
    const int gt  = blockIdx.x*blockDim.x + threadIdx.x;
    const int e   = gt >> 3;
    const int sub = threadIdx.x & 7;

    int src, dst;
    if (g_idx64){
        const long long* ei = (const long long*)ei_raw;
        src = (int)__ldg(ei + e);
        dst = (int)__ldg(ei + NE + e);
    } else {
        const int* ei = (const int*)ei_raw;
        src = __ldg(ei + e);
        dst = __ldg(ei + NE + e);
    }
    src = min(max(src, 0), NN-1);
    dst = min(max(dst, 0), NN-1);

    const uint4*  qp = reinterpret_cast<const uint4*>(g_qh) + (size_t)dst*8 + sub;
    const uint4*  kp = reinterpret_cast<const uint4*>(g_kh) + (size_t)src*8 + sub;
    const float4* vp = reinterpret_cast<const float4*>(g_v) + (size_t)src*16 + sub*2;

    uint4 qr = *qp;                    // 8 halves (8 channels)
    uint4 kr = *kp;
    float4 v0 = vp[0], v1 = vp[1];

    float d = 0.f;
    #pragma unroll
    for (int j = 0; j < 4; j++){
        float2 qf = __half22float2(reinterpret_cast<const __half2*>(&qr)[j]);
        float2 kf = __half22float2(reinterpret_cast<const __half2*>(&kr)[j]);
        d += qf.x*kf.x + qf.y*kf.y;
    }
    d += __shfl_xor_sync(0xffffffffu, d, 4);
    d += __shfl_xor_sync(0xffffffffu, d, 2);
    d += __shfl_xor_sync(0xffffffffu, d, 1);
    const float ex = __expf(d * 0.125f);   // 1/sqrt(64)

    if (sub == 0) atomicAdd(g_den + dst, ex);

    float* ap = g_agg + (size_t)dst*CH + sub*8;
    asm volatile("red.global.add.v4.f32 [%0], {%1, %2, %3, %4};"
        :: "l"(ap),     "f"(ex*v0.x), "f"(ex*v0.y), "f"(ex*v0.z), "f"(ex*v0.w) : "memory");
    asm volatile("red.global.add.v4.f32 [%0], {%1, %2, %3, %4};"
        :: "l"(ap + 4), "f"(ex*v1.x), "f"(ex*v1.y), "f"(ex*v1.z), "f"(ex*v1.w) : "memory");
}

// ---------------------------------------------------------------------------
// out_pre = agg/(den+1e-16) + skip ; global sum/sumsq
// ---------------------------------------------------------------------------
__global__ void k_final1(float* __restrict__ out){
    float lsum = 0.f, lsq = 0.f;
    const float4* agg4  = reinterpret_cast<const float4*>(g_agg);
    const float4* skip4 = reinterpret_cast<const float4*>(g_skip);
    float4* out4 = reinterpret_cast<float4*>(out);
    for (int i = blockIdx.x*blockDim.x + threadIdx.x; i < NN*16;
         i += gridDim.x*blockDim.x){
        float4 a = agg4[i];
        float4 s = skip4[i];
        const float inv = 1.f / (g_den[i>>4] + 1e-16f);
        float4 val;
        val.x = a.x*inv + s.x;  val.y = a.y*inv + s.y;
        val.z = a.z*inv + s.z;  val.w = a.w*inv + s.w;
        out4[i] = val;
        lsum += val.x + val.y + val.z + val.w;
        lsq  += val.x*val.x + val.y*val.y + val.z*val.z + val.w*val.w;
    }
    #pragma unroll
    for (int off=16; off>0; off>>=1){
        lsum += __shfl_xor_sync(0xffffffffu, lsum, off);
        lsq  += __shfl_xor_sync(0xffffffffu, lsq,  off);
    }
    __shared__ float s1[8], s2[8];
    const int wid = threadIdx.x >> 5;
    if ((threadIdx.x & 31) == 0){ s1[wid] = lsum; s2[wid] = lsq; }
    __syncthreads();
    if (threadIdx.x == 0){
        float ts = 0.f, tq = 0.f;
        #pragma unroll
        for (int i=0;i<8;i++){ ts += s1[i]; tq += s2[i]; }
        atomicAdd(&g_red[0], (double)ts);
        atomicAdd(&g_red[1], (double)tq);
    }
}

// ---------------------------------------------------------------------------
// graph layernorm + relu
// ---------------------------------------------------------------------------
__global__ void k_final2(float* __restrict__ out,
                         const float* __restrict__ lnw,
                         const float* __restrict__ lnb){
    const int i = blockIdx.x*blockDim.x + threadIdx.x;
    if (i >= NN*16) return;
    const double invM = 1.0 / (double)(NN*CH);
    const float mean = (float)(g_red[0]*invM);
    const float var  = (float)(g_red[1]*invM) - mean*mean;
    const float rstd = 1.f / (sqrtf(fmaxf(var, 0.f)) + 1e-5f);
    const int cb = (i & 15) * 4;
    const float4 wv = *reinterpret_cast<const float4*>(lnw + cb);
    const float4 bv = *reinterpret_cast<const float4*>(lnb + cb);
    float4 x = reinterpret_cast<float4*>(out)[i];
    float4 y;
    y.x = fmaxf((x.x - mean)*rstd*wv.x + bv.x, 0.f);
    y.y = fmaxf((x.y - mean)*rstd*wv.y + bv.y, 0.f);
    y.z = fmaxf((x.z - mean)*rstd*wv.z + bv.z, 0.f);
    y.w = fmaxf((x.w - mean)*rstd*wv.w + bv.w, 0.f);
    reinterpret_cast<float4*>(out)[i] = y;
}

// ---------------------------------------------------------------------------
extern "C" void kernel_launch(void* const* d_in, const int* in_sizes, int n_in,
                              void* d_out, int out_size){
    const float* geo = (const float*)d_in[0];
    const float* euc = (const float*)d_in[1];
    const float* Wq  = (const float*)d_in[2];
    const float* bq  = (const float*)d_in[3];
    const float* Wk  = (const float*)d_in[4];
    const float* bk  = (const float*)d_in[5];
    const float* Wv  = (const float*)d_in[6];
    const float* bv  = (const float*)d_in[7];
    const float* Ws  = (const float*)d_in[8];
    const float* bs  = (const float*)d_in[9];
    const float* lnw = (const float*)d_in[10];
    const float* lnb = (const float*)d_in[11];

    const void* ei = d_in[12];
    for (int i = 0; i < n_in; i++)
        if (in_sizes[i] == 2*NE){ ei = d_in[i]; break; }

    float* out = (float*)d_out;

    cudaFuncSetAttribute(k_qkvs, cudaFuncAttributeMaxDynamicSharedMemorySize,
                         QKV_SMEM_BYTES);

    k_zero   <<<NN*16/256, 256>>>();
    k_detect <<<1, 32>>>((const unsigned int*)ei);
    k_qkvs   <<<296, 256, QKV_SMEM_BYTES>>>(geo, euc, Wq, Wk, Wv, Ws,
                                            bq, bk, bv, bs);
    k_edge   <<<NE*8/256, 256>>>(ei);
    k_final1 <<<592, 256>>>(out);
    k_final2 <<<(NN*16 + 255)/256, 256>>>(out, lnw, lnb);
}

// round 9
// speedup vs baseline: 2.1605x; 1.0207x over previous
#include <cuda_runtime.h>
#include <cuda_fp16.h>

#define NN 100000
#define NE 1600000
#define CH 64
#define NT 128                 // nodes per qkvs tile
#define NTILES 782             // ceil(NN/NT)
#define WMAT 4416              // floats per matrix in w_s (64*68 + skew pad)
#define XSZ  8512              // x tile floats (64*132 + skew pad)

typedef unsigned long long ull;

// Scratch (device globals — no allocation allowed)
__device__ __align__(16) __half g_qh[NN*CH];   // fp16 q
__device__ __align__(16) __half g_kh[NN*CH];   // fp16 k
__device__ __align__(16) __half g_vh[NN*CH];   // fp16 v
__device__ __align__(16) float g_skip[NN*CH];
__device__ __align__(16) float g_agg[NN*CH];
__device__ float g_den[NN];
__device__ double g_red[2];
__device__ int g_idx64;

__device__ __forceinline__ ull ffma2(ull a, ull b, ull c){
    ull d;
    asm("fma.rn.f32x2 %0, %1, %2, %3;" : "=l"(d) : "l"(a), "l"(b), "l"(c));
    return d;
}
__device__ __forceinline__ ull splat2(float f){
    ull r;
    asm("mov.b64 %0, {%1, %1};" : "=l"(r) : "f"(f));
    return r;
}
__device__ __forceinline__ void unpack2(ull a, float& lo, float& hi){
    asm("mov.b64 {%0, %1}, %2;" : "=f"(lo), "=f"(hi) : "l"(a));
}
__device__ __forceinline__ uint2 pack_h4(float4 f){
    __half2 a01 = __floats2half2_rn(f.x, f.y);
    __half2 a23 = __floats2half2_rn(f.z, f.w);
    uint2 u;
    u.x = *reinterpret_cast<unsigned*>(&a01);
    u.y = *reinterpret_cast<unsigned*>(&a23);
    return u;
}

// ---------------------------------------------------------------------------
// zero accumulators + reduction cells
// ---------------------------------------------------------------------------
__global__ void k_zero(){
    int i = blockIdx.x*blockDim.x + threadIdx.x;          // NN*16 float4
    reinterpret_cast<float4*>(g_agg)[i] = make_float4(0.f,0.f,0.f,0.f);
    if (i < NN/4)
        reinterpret_cast<float4*>(g_den)[i] = make_float4(0.f,0.f,0.f,0.f);
    if (i == 0){ g_red[0] = 0.0; g_red[1] = 0.0; }
}

// ---------------------------------------------------------------------------
// detect dtype of edge_index (int64 vs int32), 1 warp
// ---------------------------------------------------------------------------
__global__ void k_detect(const unsigned int* __restrict__ ei32){
    unsigned int hi = ei32[2*threadIdx.x + 1];
    unsigned int b = __ballot_sync(0xffffffffu, hi != 0u);
    if (threadIdx.x == 0) g_idx64 = (b == 0u);
}

// ---------------------------------------------------------------------------
// qkvs v8: register-tiled GEMM (4ch x 8node x 2mat = 64 fp32 acc / thread),
// skewed smem. Outputs: q,k,v -> fp16 ; skip -> fp32.
// ---------------------------------------------------------------------------
#define QKV_SMEM_BYTES ((4*WMAT + XSZ + 256)*4)

__global__ void __launch_bounds__(256, 2) k_qkvs(
    const float* __restrict__ geo, const float* __restrict__ euc,
    const float* __restrict__ Wq, const float* __restrict__ Wk,
    const float* __restrict__ Wv, const float* __restrict__ Wsk,
    const float* __restrict__ bq, const float* __restrict__ bk,
    const float* __restrict__ bv, const float* __restrict__ bsk)
{
    extern __shared__ float sm[];
    float* w_s = sm;                       // [4][WMAT]  w[m][kk][c] skewed
    float* x_s = sm + 4*WMAT;              // [XSZ]      x[kk][nl]   skewed
    float* b_s = x_s + XSZ;                // [4][64]

    const int tid = threadIdx.x;

    // stage W transposed+skewed (one-time)
    {
        const float4* Wsrc[4] = {(const float4*)Wq, (const float4*)Wk,
                                 (const float4*)Wv, (const float4*)Wsk};
        #pragma unroll
        for (int j = 0; j < 16; j++){
            int f = j*256 + tid;           // 0..4095
            int m = f >> 10, r = f & 1023;
            int c = r >> 4, kc = r & 15;
            float4 v = Wsrc[m][c*16 + kc];
            float* wb = w_s + m*WMAT + 276*kc + c;
            wb[0]   = v.x;
            wb[68]  = v.y;
            wb[136] = v.z;
            wb[204] = v.w;
        }
        if (tid < 64){
            b_s[tid]       = bq[tid];
            b_s[64 + tid]  = bk[tid];
            b_s[128 + tid] = bv[tid];
            b_s[192 + tid] = bsk[tid];
        }
    }

    const int cg = tid >> 4;               // 0..15 -> c0 = 4*cg
    const int ng = tid & 15;               // 0..15 -> n0 = 8*ng
    const int c0 = cg*4;

    #pragma unroll 1
    for (int t = blockIdx.x; t < NTILES; t += gridDim.x){
        const int base = t*NT;
        #pragma unroll 1
        for (int ph = 0; ph < 2; ph++){
            const float* X = ph ? geo : euc;
            const int mA = ph ? 1 : 0;      // k : q   (fp16 out)
            const int mB = ph ? 2 : 3;      // v : skip
            __half* OA   = ph ? g_kh : g_qh;

            __syncthreads();                // x_s free from previous readers
            #pragma unroll
            for (int j = 0; j < 8; j++){
                int f = j*256 + tid;        // 0..2047
                int nl = f >> 4;            // 0..127
                int kc = f & 15;
                int node = min(base + nl, NN-1);
                float4 v = *reinterpret_cast<const float4*>(
                    X + (size_t)node*CH + kc*4);
                float* xb = x_s + 532*kc + nl;
                xb[0]   = v.x;
                xb[132] = v.y;
                xb[264] = v.z;
                xb[396] = v.w;
            }
            __syncthreads();

            ull acc[2][4][4];
            #pragma unroll
            for (int a = 0; a < 2; a++)
                #pragma unroll
                for (int b = 0; b < 4; b++)
                    #pragma unroll
                    for (int c = 0; c < 4; c++) acc[a][b][c] = 0ull;

            const float* wArow = w_s + mA*WMAT + c0;
            const float* wBrow = w_s + mB*WMAT + c0;
            const float* xrow  = x_s + ng*8;

            #pragma unroll 8
            for (int kk = 0; kk < 64; kk++){
                const int xo = kk*132 + (kk>>2)*4;
                const int wo = kk*68  + (kk>>2)*4;
                ulonglong2 xa = *reinterpret_cast<const ulonglong2*>(xrow + xo);
                ulonglong2 xb = *reinterpret_cast<const ulonglong2*>(xrow + xo + 4);
                float4 wA = *reinterpret_cast<const float4*>(wArow + wo);
                float4 wB = *reinterpret_cast<const float4*>(wBrow + wo);
                #pragma unroll
                for (int ci = 0; ci < 4; ci++){
                    ull sA = splat2((&wA.x)[ci]);
                    acc[0][ci][0] = ffma2(xa.x, sA, acc[0][ci][0]);
                    acc[0][ci][1] = ffma2(xa.y, sA, acc[0][ci][1]);
                    acc[0][ci][2] = ffma2(xb.x, sA, acc[0][ci][2]);
                    acc[0][ci][3] = ffma2(xb.y, sA, acc[0][ci][3]);
                }
                #pragma unroll
                for (int ci = 0; ci < 4; ci++){
                    ull sB = splat2((&wB.x)[ci]);
                    acc[1][ci][0] = ffma2(xa.x, sB, acc[1][ci][0]);
                    acc[1][ci][1] = ffma2(xa.y, sB, acc[1][ci][1]);
                    acc[1][ci][2] = ffma2(xb.x, sB, acc[1][ci][2]);
                    acc[1][ci][3] = ffma2(xb.y, sB, acc[1][ci][3]);
                }
            }

            // epilogue: bias; A -> fp16; B -> fp16 (v) or fp32 (skip)
            float biasA[4], biasB[4];
            #pragma unroll
            for (int ci = 0; ci < 4; ci++){
                biasA[ci] = b_s[mA*64 + c0 + ci];
                biasB[ci] = b_s[mB*64 + c0 + ci];
            }
            const int n0 = base + ng*8;
            #pragma unroll
            for (int np = 0; np < 4; np++){
                float4 loA, hiA, loB, hiB;
                #pragma unroll
                for (int ci = 0; ci < 4; ci++){
                    float lo, hi;
                    unpack2(acc[0][ci][np], lo, hi);
                    (&loA.x)[ci] = lo + biasA[ci];
                    (&hiA.x)[ci] = hi + biasA[ci];
                    unpack2(acc[1][ci][np], lo, hi);
                    (&loB.x)[ci] = lo + biasB[ci];
                    (&hiB.x)[ci] = hi + biasB[ci];
                }
                const int nlo = n0 + 2*np, nhi = n0 + 2*np + 1;
                if (nlo < NN){
                    *reinterpret_cast<uint2*>(OA + (size_t)nlo*CH + c0) = pack_h4(loA);
                    if (ph)
                        *reinterpret_cast<uint2*>(g_vh + (size_t)nlo*CH + c0) = pack_h4(loB);
                    else
                        *reinterpret_cast<float4*>(g_skip + (size_t)nlo*CH + c0) = loB;
                }
                if (nhi < NN){
                    *reinterpret_cast<uint2*>(OA + (size_t)nhi*CH + c0) = pack_h4(hiA);
                    if (ph)
                        *reinterpret_cast<uint2*>(g_vh + (size_t)nhi*CH + c0) = pack_h4(hiB);
                    else
                        *reinterpret_cast<float4*>(g_skip + (size_t)nhi*CH + c0) = hiB;
                }
            }
        }
    }
}

// ---------------------------------------------------------------------------
// fused edge pass, 8 lanes/edge, fp16 q/k/v (each row = 128B = one LDG.128
// per lane-group). Per edge L2 read bytes: 3*128; RED fp32 256B.
// ---------------------------------------------------------------------------
__global__ void k_edge(const void* __restrict__ ei_raw){
    const int gt  = blockIdx.x*blockDim.x + threadIdx.x;
    const int e   = gt >> 3;
    const int sub = threadIdx.x & 7;

    int src, dst;
    if (g_idx64){
        const long long* ei = (const long long*)ei_raw;
        src = (int)__ldg(ei + e);
        dst = (int)__ldg(ei + NE + e);
    } else {
        const int* ei = (const int*)ei_raw;
        src = __ldg(ei + e);
        dst = __ldg(ei + NE + e);
    }
    src = min(max(src, 0), NN-1);
    dst = min(max(dst, 0), NN-1);

    const uint4* qp = reinterpret_cast<const uint4*>(g_qh) + (size_t)dst*8 + sub;
    const uint4* kp = reinterpret_cast<const uint4*>(g_kh) + (size_t)src*8 + sub;
    const uint4* vp = reinterpret_cast<const uint4*>(g_vh) + (size_t)src*8 + sub;

    uint4 qr = *qp;                    // 8 halves (8 channels)
    uint4 kr = *kp;
    uint4 vr = *vp;

    float d = 0.f;
    #pragma unroll
    for (int j = 0; j < 4; j++){
        float2 qf = __half22float2(reinterpret_cast<const __half2*>(&qr)[j]);
        float2 kf = __half22float2(reinterpret_cast<const __half2*>(&kr)[j]);
        d += qf.x*kf.x + qf.y*kf.y;
    }
    d += __shfl_xor_sync(0xffffffffu, d, 4);
    d += __shfl_xor_sync(0xffffffffu, d, 2);
    d += __shfl_xor_sync(0xffffffffu, d, 1);
    const float ex = __expf(d * 0.125f);   // 1/sqrt(64)

    if (sub == 0) atomicAdd(g_den + dst, ex);

    float2 vf0 = __half22float2(reinterpret_cast<const __half2*>(&vr)[0]);
    float2 vf1 = __half22float2(reinterpret_cast<const __half2*>(&vr)[1]);
    float2 vf2 = __half22float2(reinterpret_cast<const __half2*>(&vr)[2]);
    float2 vf3 = __half22float2(reinterpret_cast<const __half2*>(&vr)[3]);

    float* ap = g_agg + (size_t)dst*CH + sub*8;
    asm volatile("red.global.add.v4.f32 [%0], {%1, %2, %3, %4};"
        :: "l"(ap),     "f"(ex*vf0.x), "f"(ex*vf0.y), "f"(ex*vf1.x), "f"(ex*vf1.y) : "memory");
    asm volatile("red.global.add.v4.f32 [%0], {%1, %2, %3, %4};"
        :: "l"(ap + 4), "f"(ex*vf2.x), "f"(ex*vf2.y), "f"(ex*vf3.x), "f"(ex*vf3.y) : "memory");
}

// ---------------------------------------------------------------------------
// out_pre = agg/(den+1e-16) + skip ; global sum/sumsq
// ---------------------------------------------------------------------------
__global__ void k_final1(float* __restrict__ out){
    float lsum = 0.f, lsq = 0.f;
    const float4* agg4  = reinterpret_cast<const float4*>(g_agg);
    const float4* skip4 = reinterpret_cast<const float4*>(g_skip);
    float4* out4 = reinterpret_cast<float4*>(out);
    for (int i = blockIdx.x*blockDim.x + threadIdx.x; i < NN*16;
         i += gridDim.x*blockDim.x){
        float4 a = agg4[i];
        float4 s = skip4[i];
        const float inv = 1.f / (g_den[i>>4] + 1e-16f);
        float4 val;
        val.x = a.x*inv + s.x;  val.y = a.y*inv + s.y;
        val.z = a.z*inv + s.z;  val.w = a.w*inv + s.w;
        out4[i] = val;
        lsum += val.x + val.y + val.z + val.w;
        lsq  += val.x*val.x + val.y*val.y + val.z*val.z + val.w*val.w;
    }
    #pragma unroll
    for (int off=16; off>0; off>>=1){
        lsum += __shfl_xor_sync(0xffffffffu, lsum, off);
        lsq  += __shfl_xor_sync(0xffffffffu, lsq,  off);
    }
    __shared__ float s1[8], s2[8];
    const int wid = threadIdx.x >> 5;
    if ((threadIdx.x & 31) == 0){ s1[wid] = lsum; s2[wid] = lsq; }
    __syncthreads();
    if (threadIdx.x == 0){
        float ts = 0.f, tq = 0.f;
        #pragma unroll
        for (int i=0;i<8;i++){ ts += s1[i]; tq += s2[i]; }
        atomicAdd(&g_red[0], (double)ts);
        atomicAdd(&g_red[1], (double)tq);
    }
}

// ---------------------------------------------------------------------------
// graph layernorm + relu
// ---------------------------------------------------------------------------
__global__ void k_final2(float* __restrict__ out,
                         const float* __restrict__ lnw,
                         const float* __restrict__ lnb){
    const int i = blockIdx.x*blockDim.x + threadIdx.x;
    if (i >= NN*16) return;
    const double invM = 1.0 / (double)(NN*CH);
    const float mean = (float)(g_red[0]*invM);
    const float var  = (float)(g_red[1]*invM) - mean*mean;
    const float rstd = 1.f / (sqrtf(fmaxf(var, 0.f)) + 1e-5f);
    const int cb = (i & 15) * 4;
    const float4 wv = *reinterpret_cast<const float4*>(lnw + cb);
    const float4 bv = *reinterpret_cast<const float4*>(lnb + cb);
    float4 x = reinterpret_cast<float4*>(out)[i];
    float4 y;
    y.x = fmaxf((x.x - mean)*rstd*wv.x + bv.x, 0.f);
    y.y = fmaxf((x.y - mean)*rstd*wv.y + bv.y, 0.f);
    y.z = fmaxf((x.z - mean)*rstd*wv.z + bv.z, 0.f);
    y.w = fmaxf((x.w - mean)*rstd*wv.w + bv.w, 0.f);
    reinterpret_cast<float4*>(out)[i] = y;
}

// ---------------------------------------------------------------------------
extern "C" void kernel_launch(void* const* d_in, const int* in_sizes, int n_in,
                              void* d_out, int out_size){
    const float* geo = (const float*)d_in[0];
    const float* euc = (const float*)d_in[1];
    const float* Wq  = (const float*)d_in[2];
    const float* bq  = (const float*)d_in[3];
    const float* Wk  = (const float*)d_in[4];
    const float* bk  = (const float*)d_in[5];
    const float* Wv  = (const float*)d_in[6];
    const float* bv  = (const float*)d_in[7];
    const float* Ws  = (const float*)d_in[8];
    const float* bs  = (const float*)d_in[9];
    const float* lnw = (const float*)d_in[10];
    const float* lnb = (const float*)d_in[11];

    const void* ei = d_in[12];
    for (int i = 0; i < n_in; i++)
        if (in_sizes[i] == 2*NE){ ei = d_in[i]; break; }

    float* out = (float*)d_out;

    cudaFuncSetAttribute(k_qkvs, cudaFuncAttributeMaxDynamicSharedMemorySize,
                         QKV_SMEM_BYTES);

    k_zero   <<<NN*16/256, 256>>>();
    k_detect <<<1, 32>>>((const unsigned int*)ei);
    k_qkvs   <<<296, 256, QKV_SMEM_BYTES>>>(geo, euc, Wq, Wk, Wv, Ws,
                                            bq, bk, bv, bs);
    k_edge   <<<NE*8/256, 256>>>(ei);
    k_final1 <<<592, 256>>>(out);
    k_final2 <<<(NN*16 + 255)/256, 256>>>(out, lnw, lnb);
}